// round 1
// baseline (speedup 1.0000x reference)
#include <cuda_runtime.h>
#include <math.h>

#define BB 2
#define SS 2048
#define EE 1024
#define HH 16
#define HD 64
#define MTOT (BB*SS)
#define SCALE 0.125f   // 1/sqrt(64)

// Scratch: device globals (allocation-free rule)
__device__ float g_q[MTOT * EE];
__device__ float g_k[MTOT * EE];
__device__ float g_v[MTOT * EE];
__device__ float g_att[MTOT * EE];

// ---------------------------------------------------------------------------
// GEMM: C[M,N] = A[M,K] @ W[N,K]^T + bias[N]
// 64x64 tile, BK=16, 256 threads, 4x4 per thread.
// ---------------------------------------------------------------------------
__global__ __launch_bounds__(256) void gemm_bias_kernel(
    const float* __restrict__ A, const float* __restrict__ W,
    const float* __restrict__ bias, float* __restrict__ C, int Kdim)
{
    __shared__ float As[16][65];
    __shared__ float Bs[16][65];
    const int tid = threadIdx.x;
    const int tx = tid & 15;        // n-group
    const int ty = tid >> 4;        // m-group
    const int bn = blockIdx.x * 64;
    const int bm = blockIdx.y * 64;

    float acc[4][4] = {};
    const float* Ap = A + (size_t)bm * Kdim;
    const float* Wp = W + (size_t)bn * Kdim;

    for (int k0 = 0; k0 < Kdim; k0 += 16) {
        #pragma unroll
        for (int i = 0; i < 4; i++) {
            int id = tid + i * 256;
            int m = id >> 4, k = id & 15;
            As[k][m] = Ap[(size_t)m * Kdim + k0 + k];
            Bs[k][m] = Wp[(size_t)m * Kdim + k0 + k];
        }
        __syncthreads();
        #pragma unroll
        for (int k = 0; k < 16; k++) {
            float ra[4], rb[4];
            #pragma unroll
            for (int i = 0; i < 4; i++) ra[i] = As[k][ty * 4 + i];
            #pragma unroll
            for (int j = 0; j < 4; j++) rb[j] = Bs[k][tx * 4 + j];
            #pragma unroll
            for (int i = 0; i < 4; i++)
                #pragma unroll
                for (int j = 0; j < 4; j++)
                    acc[i][j] = fmaf(ra[i], rb[j], acc[i][j]);
        }
        __syncthreads();
    }

    #pragma unroll
    for (int i = 0; i < 4; i++) {
        int m = bm + ty * 4 + i;
        #pragma unroll
        for (int j = 0; j < 4; j++) {
            int n = bn + tx * 4 + j;
            C[(size_t)m * EE + n] = acc[i][j] + bias[n];
        }
    }
}

// ---------------------------------------------------------------------------
// Flash attention: one block = (b, h, 64 q-rows), 64 threads, 1 thread/row.
// Q row pre-scaled in registers, K/V tiles staged in shared (reused buffer),
// probabilities staged in Ps[64][65] (conflict-free per-row).
// ---------------------------------------------------------------------------
__global__ __launch_bounds__(64) void attn_kernel()
{
    __shared__ float KVs[64][64];
    __shared__ float Ps[64][65];

    const int r  = threadIdx.x;
    const int bh = blockIdx.x;
    const int b  = bh >> 4;
    const int h  = bh & 15;
    const int q0 = blockIdx.y * 64;

    // Load this thread's Q row into registers (pre-scaled). One-time cost,
    // amortized over all 32 KV tiles.
    float qreg[64];
    {
        const float* qrow = g_q + ((size_t)(b * SS + q0 + r)) * EE + h * HD;
        #pragma unroll
        for (int c = 0; c < 64; c++) qreg[c] = qrow[c] * SCALE;
    }

    float o[64];
    #pragma unroll
    for (int d = 0; d < 64; d++) o[d] = 0.f;
    float m = -1e30f, l = 0.f;

    const float* kbase = g_k + ((size_t)b * SS) * EE + h * HD;
    const float* vbase = g_v + ((size_t)b * SS) * EE + h * HD;

    for (int kt = 0; kt < SS / 64; kt++) {
        // Load K tile (coalesced: 64 lanes read 64 consecutive floats per row)
        for (int j = 0; j < 64; j++)
            KVs[j][r] = kbase[(size_t)(kt * 64 + j) * EE + r];
        __syncthreads();

        // Scores: s_j = (q/sqrt(hd)) . k_j   (2 accumulators to break chain)
        float mloc = m;
        for (int j = 0; j < 64; j++) {
            const float4* kv4 = (const float4*)KVs[j];
            float a0 = 0.f, a1 = 0.f;
            #pragma unroll
            for (int c4 = 0; c4 < 16; c4 += 2) {
                float4 k0v = kv4[c4];
                float4 k1v = kv4[c4 + 1];
                a0 = fmaf(qreg[c4 * 4 + 0], k0v.x, a0);
                a0 = fmaf(qreg[c4 * 4 + 1], k0v.y, a0);
                a0 = fmaf(qreg[c4 * 4 + 2], k0v.z, a0);
                a0 = fmaf(qreg[c4 * 4 + 3], k0v.w, a0);
                a1 = fmaf(qreg[c4 * 4 + 4], k1v.x, a1);
                a1 = fmaf(qreg[c4 * 4 + 5], k1v.y, a1);
                a1 = fmaf(qreg[c4 * 4 + 6], k1v.z, a1);
                a1 = fmaf(qreg[c4 * 4 + 7], k1v.w, a1);
            }
            float s = a0 + a1;
            Ps[r][j] = s;
            mloc = fmaxf(mloc, s);
        }

        // Online softmax update
        float corr = __expf(m - mloc);
        float lsum = 0.f;
        for (int j = 0; j < 64; j++) {
            float p = __expf(Ps[r][j] - mloc);
            Ps[r][j] = p;
            lsum += p;
        }
        l = l * corr + lsum;
        m = mloc;
        #pragma unroll
        for (int d = 0; d < 64; d++) o[d] *= corr;

        __syncthreads();
        // Load V tile into the same buffer
        for (int j = 0; j < 64; j++)
            KVs[j][r] = vbase[(size_t)(kt * 64 + j) * EE + r];
        __syncthreads();

        // O += P . V
        for (int j = 0; j < 64; j++) {
            float pj = Ps[r][j];
            const float4* vv4 = (const float4*)KVs[j];
            #pragma unroll
            for (int d4 = 0; d4 < 16; d4++) {
                float4 vv = vv4[d4];
                o[d4 * 4 + 0] = fmaf(pj, vv.x, o[d4 * 4 + 0]);
                o[d4 * 4 + 1] = fmaf(pj, vv.y, o[d4 * 4 + 1]);
                o[d4 * 4 + 2] = fmaf(pj, vv.z, o[d4 * 4 + 2]);
                o[d4 * 4 + 3] = fmaf(pj, vv.w, o[d4 * 4 + 3]);
            }
        }
        __syncthreads();
    }

    // Normalize and store
    float inv = 1.f / l;
    float* obase = g_att + ((size_t)(b * SS + q0 + r)) * EE + h * HD;
    #pragma unroll
    for (int d = 0; d < 64; d++) obase[d] = o[d] * inv;
}

// ---------------------------------------------------------------------------
// Launch: 3 projection GEMMs -> attention -> output GEMM
// ---------------------------------------------------------------------------
extern "C" void kernel_launch(void* const* d_in, const int* in_sizes, int n_in,
                              void* d_out, int out_size)
{
    const float* query = (const float*)d_in[0];
    const float* key_  = (const float*)d_in[1];
    const float* value = (const float*)d_in[2];
    const float* Wq    = (const float*)d_in[3];
    const float* bq    = (const float*)d_in[4];
    const float* Wk    = (const float*)d_in[5];
    const float* bk    = (const float*)d_in[6];
    const float* Wv    = (const float*)d_in[7];
    const float* bv    = (const float*)d_in[8];
    const float* Wo    = (const float*)d_in[9];
    const float* bo    = (const float*)d_in[10];
    float* out = (float*)d_out;

    float *q, *k, *v, *att;
    cudaGetSymbolAddress((void**)&q,   g_q);
    cudaGetSymbolAddress((void**)&k,   g_k);
    cudaGetSymbolAddress((void**)&v,   g_v);
    cudaGetSymbolAddress((void**)&att, g_att);

    dim3 gg(EE / 64, MTOT / 64);
    gemm_bias_kernel<<<gg, 256>>>(query, Wq, bq, q, EE);
    gemm_bias_kernel<<<gg, 256>>>(key_,  Wk, bk, k, EE);
    gemm_bias_kernel<<<gg, 256>>>(value, Wv, bv, v, EE);

    attn_kernel<<<dim3(BB * HH, SS / 64), 64>>>();

    gemm_bias_kernel<<<gg, 256>>>(att, Wo, bo, out, EE);
}

// round 2
// speedup vs baseline: 4.8837x; 4.8837x over previous
#include <cuda_runtime.h>
#include <math.h>

#define BB 2
#define SS 2048
#define EE 1024
#define HH 16
#define HD 64
#define MTOT (BB*SS)
#define SCALE 0.125f   // 1/sqrt(64)

// Scratch (allocation-free rule): device globals
__device__ float g_q[MTOT * EE];
__device__ float g_k[MTOT * EE];
__device__ float g_v[MTOT * EE];
__device__ float g_att[MTOT * EE];

// ---------------------------------------------------------------------------
// tf32 helpers
// ---------------------------------------------------------------------------
__device__ __forceinline__ unsigned f2tf(float f) {
    unsigned r;
    asm("cvt.rna.tf32.f32 %0, %1;" : "=r"(r) : "f"(f));
    return r;
}

__device__ __forceinline__ void mma_tf32(float c[4], const unsigned a[4], const unsigned b[2]) {
    asm volatile(
        "mma.sync.aligned.m16n8k8.row.col.f32.tf32.tf32.f32 "
        "{%0,%1,%2,%3}, {%4,%5,%6,%7}, {%8,%9}, {%0,%1,%2,%3};"
        : "+f"(c[0]), "+f"(c[1]), "+f"(c[2]), "+f"(c[3])
        : "r"(a[0]), "r"(a[1]), "r"(a[2]), "r"(a[3]), "r"(b[0]), "r"(b[1]));
}

// ---------------------------------------------------------------------------
// GEMM: C[M,N] = A[M,K] @ W[N,K]^T + bias   (M=4096, N=K=1024)
// CTA 128x128x32, 256 threads (8 warps, 2x4), warp tile 64x32.
// smem stride 36 floats (36 % 32 == 4 -> conflict-free fragment loads).
// Register-staged double buffering (LDG next tile while computing current).
// ---------------------------------------------------------------------------
#define GSTR 36

struct QKVArgs {
    const float* A[3];
    const float* W[3];
    const float* bias[3];
    float*       C[3];
};

__device__ __forceinline__ void gemm_body(
    const float* __restrict__ A, const float* __restrict__ W,
    const float* __restrict__ bias, float* __restrict__ C)
{
    __shared__ unsigned As[128 * GSTR];
    __shared__ unsigned Bs[128 * GSTR];

    const int tid  = threadIdx.x;
    const int warp = tid >> 5, lane = tid & 31;
    const int g = lane >> 2, t = lane & 3;
    const int wm = warp & 1, wn = warp >> 1;     // 2 x 4 warps
    const int bm = blockIdx.y * 128, bn = blockIdx.x * 128;

    const float* Ap = A + (size_t)bm * EE;
    const float* Wp = W + (size_t)bn * EE;

    float4 ra[4], rb[4];
    #pragma unroll
    for (int i = 0; i < 4; i++) {
        int id = tid + i * 256; int m = id >> 3, kq = id & 7;
        ra[i] = *(const float4*)(Ap + (size_t)m * EE + kq * 4);
        rb[i] = *(const float4*)(Wp + (size_t)m * EE + kq * 4);
    }

    float acc[4][4][4] = {};

    for (int k0 = 0; k0 < EE; k0 += 32) {
        // commit staged regs to smem (convert to tf32)
        #pragma unroll
        for (int i = 0; i < 4; i++) {
            int id = tid + i * 256; int m = id >> 3, kq = id & 7;
            unsigned* p = &As[m * GSTR + kq * 4];
            p[0] = f2tf(ra[i].x); p[1] = f2tf(ra[i].y); p[2] = f2tf(ra[i].z); p[3] = f2tf(ra[i].w);
            unsigned* q = &Bs[m * GSTR + kq * 4];
            q[0] = f2tf(rb[i].x); q[1] = f2tf(rb[i].y); q[2] = f2tf(rb[i].z); q[3] = f2tf(rb[i].w);
        }
        __syncthreads();

        // prefetch next tile
        if (k0 + 32 < EE) {
            #pragma unroll
            for (int i = 0; i < 4; i++) {
                int id = tid + i * 256; int m = id >> 3, kq = id & 7;
                ra[i] = *(const float4*)(Ap + (size_t)m * EE + (k0 + 32) + kq * 4);
                rb[i] = *(const float4*)(Wp + (size_t)m * EE + (k0 + 32) + kq * 4);
            }
        }

        // compute: 4 k-steps of 8
        #pragma unroll
        for (int ks = 0; ks < 4; ks++) {
            unsigned af[4][4], bf[4][2];
            #pragma unroll
            for (int mi = 0; mi < 4; mi++) {
                int m = wm * 64 + mi * 16;
                af[mi][0] = As[(m + g)     * GSTR + ks * 8 + t];
                af[mi][1] = As[(m + g + 8) * GSTR + ks * 8 + t];
                af[mi][2] = As[(m + g)     * GSTR + ks * 8 + t + 4];
                af[mi][3] = As[(m + g + 8) * GSTR + ks * 8 + t + 4];
            }
            #pragma unroll
            for (int ni = 0; ni < 4; ni++) {
                int n = wn * 32 + ni * 8 + g;
                bf[ni][0] = Bs[n * GSTR + ks * 8 + t];
                bf[ni][1] = Bs[n * GSTR + ks * 8 + t + 4];
            }
            #pragma unroll
            for (int mi = 0; mi < 4; mi++)
                #pragma unroll
                for (int ni = 0; ni < 4; ni++)
                    mma_tf32(acc[mi][ni], af[mi], bf[ni]);
        }
        __syncthreads();
    }

    // epilogue: add bias, store
    #pragma unroll
    for (int mi = 0; mi < 4; mi++) {
        #pragma unroll
        for (int r2 = 0; r2 < 2; r2++) {
            int m = bm + wm * 64 + mi * 16 + g + r2 * 8;
            #pragma unroll
            for (int ni = 0; ni < 4; ni++) {
                int n = bn + wn * 32 + ni * 8 + 2 * t;
                float2 bv = *(const float2*)(bias + n);
                float2 o;
                o.x = acc[mi][ni][r2 * 2 + 0] + bv.x;
                o.y = acc[mi][ni][r2 * 2 + 1] + bv.y;
                *(float2*)(C + (size_t)m * EE + n) = o;
            }
        }
    }
}

__global__ __launch_bounds__(256) void qkv_gemm(QKVArgs args) {
    int z = blockIdx.z;
    gemm_body(args.A[z], args.W[z], args.bias[z], args.C[z]);
}

__global__ __launch_bounds__(256) void out_gemm(const float* __restrict__ A,
                                                const float* __restrict__ W,
                                                const float* __restrict__ bias,
                                                float* __restrict__ C) {
    gemm_body(A, W, bias, C);
}

// ---------------------------------------------------------------------------
// Flash attention with tf32 mma.
// Block = (b, h, 64 q-rows), 128 threads (4 warps, 16 rows each).
// Q kept as tf32 A-fragments in registers. smem stride 68 (68 % 32 == 4).
// ---------------------------------------------------------------------------
#define ASTR 68

__global__ __launch_bounds__(128) void attn_tc() {
    extern __shared__ unsigned smem[];
    unsigned* Ks = smem;                // 64*68
    unsigned* Vs = smem + 64 * ASTR;    // 64*68
    unsigned* Ps = smem + 2 * 64 * ASTR;// 64*68 (Q staging, then P tiles)

    const int tid  = threadIdx.x;
    const int warp = tid >> 5, lane = tid & 31;
    const int g = lane >> 2, t = lane & 3;
    const int bh = blockIdx.x;
    const int b = bh >> 4, h = bh & 15;
    const int q0 = blockIdx.y * 64;

    const size_t base = (size_t)b * SS * EE + (size_t)h * HD;

    // ---- stage Q (scaled, tf32) through Ps, then pull A-fragments to regs
    {
        const float* qp = g_q + base + (size_t)q0 * EE;
        #pragma unroll
        for (int i = 0; i < 8; i++) {
            int id = tid + i * 128;           // 1024 float4: 64 rows x 16
            int r = id >> 4, c4 = id & 15;
            float4 v = *(const float4*)(qp + (size_t)r * EE + c4 * 4);
            unsigned* p = &Ps[r * ASTR + c4 * 4];
            p[0] = f2tf(v.x * SCALE); p[1] = f2tf(v.y * SCALE);
            p[2] = f2tf(v.z * SCALE); p[3] = f2tf(v.w * SCALE);
        }
    }
    __syncthreads();

    unsigned qf[8][4];
    {
        int m = warp * 16;
        #pragma unroll
        for (int ks = 0; ks < 8; ks++) {
            qf[ks][0] = Ps[(m + g)     * ASTR + ks * 8 + t];
            qf[ks][1] = Ps[(m + g + 8) * ASTR + ks * 8 + t];
            qf[ks][2] = Ps[(m + g)     * ASTR + ks * 8 + t + 4];
            qf[ks][3] = Ps[(m + g + 8) * ASTR + ks * 8 + t + 4];
        }
    }
    __syncthreads();

    float o[8][4] = {};
    float mrow0 = -1e30f, mrow1 = -1e30f, lrow0 = 0.f, lrow1 = 0.f;

    const float* kp = g_k + base;
    const float* vp = g_v + base;

    for (int kt = 0; kt < SS / 64; kt++) {
        // ---- load K,V tiles (tf32)
        #pragma unroll
        for (int i = 0; i < 8; i++) {
            int id = tid + i * 128; int r = id >> 4, c4 = id & 15;
            size_t go = (size_t)(kt * 64 + r) * EE + c4 * 4;
            float4 kv = *(const float4*)(kp + go);
            float4 vv = *(const float4*)(vp + go);
            unsigned* pk = &Ks[r * ASTR + c4 * 4];
            pk[0] = f2tf(kv.x); pk[1] = f2tf(kv.y); pk[2] = f2tf(kv.z); pk[3] = f2tf(kv.w);
            unsigned* pv = &Vs[r * ASTR + c4 * 4];
            pv[0] = f2tf(vv.x); pv[1] = f2tf(vv.y); pv[2] = f2tf(vv.z); pv[3] = f2tf(vv.w);
        }
        __syncthreads();

        // ---- S = Q @ K^T  (per warp: 16 x 64)
        float s[8][4] = {};
        #pragma unroll
        for (int ks = 0; ks < 8; ks++) {
            #pragma unroll
            for (int ni = 0; ni < 8; ni++) {
                unsigned bf[2];
                int n = ni * 8 + g;                       // kv index
                bf[0] = Ks[n * ASTR + ks * 8 + t];
                bf[1] = Ks[n * ASTR + ks * 8 + t + 4];
                mma_tf32(s[ni], qf[ks], bf);
            }
        }

        // ---- online softmax (rows g and g+8; reduce over the 4 lanes of t)
        float mx0 = -1e30f, mx1 = -1e30f;
        #pragma unroll
        for (int ni = 0; ni < 8; ni++) {
            mx0 = fmaxf(mx0, fmaxf(s[ni][0], s[ni][1]));
            mx1 = fmaxf(mx1, fmaxf(s[ni][2], s[ni][3]));
        }
        mx0 = fmaxf(mx0, __shfl_xor_sync(0xffffffffu, mx0, 1));
        mx0 = fmaxf(mx0, __shfl_xor_sync(0xffffffffu, mx0, 2));
        mx1 = fmaxf(mx1, __shfl_xor_sync(0xffffffffu, mx1, 1));
        mx1 = fmaxf(mx1, __shfl_xor_sync(0xffffffffu, mx1, 2));

        float mn0 = fmaxf(mrow0, mx0), mn1 = fmaxf(mrow1, mx1);
        float c0 = __expf(mrow0 - mn0), c1 = __expf(mrow1 - mn1);
        float sum0 = 0.f, sum1 = 0.f;
        #pragma unroll
        for (int ni = 0; ni < 8; ni++) {
            s[ni][0] = __expf(s[ni][0] - mn0);
            s[ni][1] = __expf(s[ni][1] - mn0);
            s[ni][2] = __expf(s[ni][2] - mn1);
            s[ni][3] = __expf(s[ni][3] - mn1);
            sum0 += s[ni][0] + s[ni][1];
            sum1 += s[ni][2] + s[ni][3];
        }
        sum0 += __shfl_xor_sync(0xffffffffu, sum0, 1);
        sum0 += __shfl_xor_sync(0xffffffffu, sum0, 2);
        sum1 += __shfl_xor_sync(0xffffffffu, sum1, 1);
        sum1 += __shfl_xor_sync(0xffffffffu, sum1, 2);
        lrow0 = lrow0 * c0 + sum0;  mrow0 = mn0;
        lrow1 = lrow1 * c1 + sum1;  mrow1 = mn1;
        #pragma unroll
        for (int ni = 0; ni < 8; ni++) {
            o[ni][0] *= c0; o[ni][1] *= c0;
            o[ni][2] *= c1; o[ni][3] *= c1;
        }

        // ---- write P (tf32) to warp-local rows of Ps
        {
            int m = warp * 16;
            #pragma unroll
            for (int ni = 0; ni < 8; ni++) {
                uint2 w0 = make_uint2(f2tf(s[ni][0]), f2tf(s[ni][1]));
                uint2 w1 = make_uint2(f2tf(s[ni][2]), f2tf(s[ni][3]));
                *(uint2*)&Ps[(m + g)     * ASTR + ni * 8 + 2 * t] = w0;
                *(uint2*)&Ps[(m + g + 8) * ASTR + ni * 8 + 2 * t] = w1;
            }
        }
        __syncwarp();

        // ---- O += P @ V  (A from Ps, B = Vs[j][d])
        {
            int m = warp * 16;
            #pragma unroll
            for (int ks = 0; ks < 8; ks++) {
                unsigned af[4];
                af[0] = Ps[(m + g)     * ASTR + ks * 8 + t];
                af[1] = Ps[(m + g + 8) * ASTR + ks * 8 + t];
                af[2] = Ps[(m + g)     * ASTR + ks * 8 + t + 4];
                af[3] = Ps[(m + g + 8) * ASTR + ks * 8 + t + 4];
                #pragma unroll
                for (int ni = 0; ni < 8; ni++) {
                    unsigned bf[2];
                    int n = ni * 8 + g;                   // d index
                    bf[0] = Vs[(ks * 8 + t)     * ASTR + n];
                    bf[1] = Vs[(ks * 8 + t + 4) * ASTR + n];
                    mma_tf32(o[ni], af, bf);
                }
            }
        }
        __syncthreads();   // Vs/Ks consumed before next tile load
    }

    // ---- normalize, store
    float inv0 = 1.f / lrow0, inv1 = 1.f / lrow1;
    int r0 = q0 + warp * 16 + g;
    #pragma unroll
    for (int ni = 0; ni < 8; ni++) {
        int d = h * HD + ni * 8 + 2 * t;
        float2 w0 = make_float2(o[ni][0] * inv0, o[ni][1] * inv0);
        float2 w1 = make_float2(o[ni][2] * inv1, o[ni][3] * inv1);
        *(float2*)(g_att + (size_t)(b * SS + r0)     * EE + d) = w0;
        *(float2*)(g_att + (size_t)(b * SS + r0 + 8) * EE + d) = w1;
    }
}

// ---------------------------------------------------------------------------
// Launch
// ---------------------------------------------------------------------------
extern "C" void kernel_launch(void* const* d_in, const int* in_sizes, int n_in,
                              void* d_out, int out_size)
{
    const float* query = (const float*)d_in[0];
    const float* key_  = (const float*)d_in[1];
    const float* value = (const float*)d_in[2];
    const float* Wq = (const float*)d_in[3];
    const float* bq = (const float*)d_in[4];
    const float* Wk = (const float*)d_in[5];
    const float* bk = (const float*)d_in[6];
    const float* Wv = (const float*)d_in[7];
    const float* bv = (const float*)d_in[8];
    const float* Wo = (const float*)d_in[9];
    const float* bo = (const float*)d_in[10];
    float* out = (float*)d_out;

    float *q, *k, *v, *att;
    cudaGetSymbolAddress((void**)&q,   g_q);
    cudaGetSymbolAddress((void**)&k,   g_k);
    cudaGetSymbolAddress((void**)&v,   g_v);
    cudaGetSymbolAddress((void**)&att, g_att);

    static bool attr_done = false;
    if (!attr_done) {
        cudaFuncSetAttribute(attn_tc, cudaFuncAttributeMaxDynamicSharedMemorySize,
                             3 * 64 * ASTR * 4);
        attr_done = true;
    }

    QKVArgs args;
    args.A[0] = query; args.A[1] = key_; args.A[2] = value;
    args.W[0] = Wq;    args.W[1] = Wk;   args.W[2] = Wv;
    args.bias[0] = bq; args.bias[1] = bk; args.bias[2] = bv;
    args.C[0] = q;     args.C[1] = k;    args.C[2] = v;

    dim3 gqkv(EE / 128, MTOT / 128, 3);
    qkv_gemm<<<gqkv, 256>>>(args);

    attn_tc<<<dim3(BB * HH, SS / 64), 128, 3 * 64 * ASTR * 4>>>();

    dim3 go(EE / 128, MTOT / 128);
    out_gemm<<<go, 256>>>(att, Wo, bo, out);
}